// round 12
// baseline (speedup 1.0000x reference)
#include <cuda_runtime.h>
#include <cuda_fp16.h>
#include <cstdint>

#define NB 4
#define NS 2048
#define NE 128
#define NH 16
#define ND 8
#define NBH (NB * NH)
#define KH 1024            // keys per CTA (half of NS)

// Staged head data (written by qgen, read by attn)
__device__ uint32_t g_kh[NBH * NS * 4];     // 2 MB fp16x2 CLS-scaled q/k
__device__ uint32_t g_vp[NBH * (NS/2) * 8]; // 2 MB pair-packed v*mask
__device__ float    g_num[2][NB * NS * NE]; // 8 MB partial numerators
__device__ float    g_den[2][NB * NS * NH]; // 1 MB partial denominators

__device__ __forceinline__ uint32_t ex2h2(uint32_t x) {
    uint32_t r; asm("ex2.approx.f16x2 %0,%1;" : "=r"(r) : "r"(x)); return r;
}
// score MMA: m16n8k8, fp16 accumulate -> D already packed f16x2
__device__ __forceinline__ void mma16808h(uint32_t& dlo, uint32_t& dhi,
                                          uint32_t a0, uint32_t a1, uint32_t b0) {
    asm volatile("mma.sync.aligned.m16n8k8.row.col.f16.f16.f16.f16 "
                 "{%0,%1},{%2,%3},{%4},{%5,%5};"
                 : "=r"(dlo), "=r"(dhi)
                 : "r"(a0), "r"(a1), "r"(b0), "r"(0u));
}
__device__ __forceinline__ void mma16816(float c[4],
                                         uint32_t a0, uint32_t a1, uint32_t a2, uint32_t a3,
                                         uint32_t b0, uint32_t b1) {
    asm volatile("mma.sync.aligned.m16n8k16.row.col.f32.f16.f16.f32 "
                 "{%0,%1,%2,%3},{%4,%5,%6,%7},{%8,%9},{%0,%1,%2,%3};"
                 : "+f"(c[0]), "+f"(c[1]), "+f"(c[2]), "+f"(c[3])
                 : "r"(a0), "r"(a1), "r"(a2), "r"(a3), "r"(b0), "r"(b1));
}

// ---------------------------------------------------------------------------
// Kernel A: q = cumprod(cos(x+theta)); emit sqrtCL-scaled fp16 pairs
// (score operands) + mask-folded pair-packed V.
// ---------------------------------------------------------------------------
__global__ void __launch_bounds__(128) qgen_kernel(const float* __restrict__ x,
                                                   const float* __restrict__ theta,
                                                   const int* __restrict__ mask) {
    int r = blockIdx.x * blockDim.x + threadIdx.x;   // r = bh*NS + s
    if (r >= NBH * NS) return;
    int s  = r & (NS - 1);
    int bh = r >> 11;
    int h  = bh & (NH - 1);
    int b  = bh >> 4;

    const float4* xp = (const float4*)(x + ((size_t)(b * NS + s) * NE + h * ND));
    float4 x0 = xp[0], x1 = xp[1];

    float v[8];
    float p;
    p  = cosf(x0.x + theta[0]);  v[0] = p;
    p *= cosf(x0.y + theta[1]);  v[1] = p;
    p *= cosf(x0.z + theta[2]);  v[2] = p;
    p *= cosf(x0.w + theta[3]);  v[3] = p;
    p *= cosf(x1.x + theta[4]);  v[4] = p;
    p *= cosf(x1.y + theta[5]);  v[5] = p;
    p *= cosf(x1.z + theta[6]);  v[6] = p;
    p *= cosf(x1.w + theta[7]);  v[7] = p;

    // sqrt(log2(e)/sqrt(8)) folded into BOTH score operands
    const float CLS = 0.71421430302f;   // sqrt(0.51010205144336435)
    uint32_t hw[4];
#pragma unroll
    for (int j = 0; j < 4; ++j) {
        __half h0 = __float2half_rn(v[2 * j] * CLS);
        __half h1 = __float2half_rn(v[2 * j + 1] * CLS);
        hw[j] = (uint32_t)__half_as_ushort(h0) | ((uint32_t)__half_as_ushort(h1) << 16);
    }
    ((uint4*)g_kh)[r] = make_uint4(hw[0], hw[1], hw[2], hw[3]);

    // pair-packed V with mask folded: g_vp[bh][s/2][n] = half2{v*m (even), (odd)}
    float m = (float)mask[b * NS + s];
    uint16_t* vp16 = (uint16_t*)g_vp;
    size_t base = (((size_t)bh * (NS / 2) + (s >> 1)) * 8) * 2 + (s & 1);
#pragma unroll
    for (int n = 0; n < 8; ++n)
        vp16[base + 2 * n] = __half_as_ushort(__float2half_rn(v[n] * m));
}

// ---------------------------------------------------------------------------
// Kernel B: HMMA flash attention, key-split for occupancy (unchanged from R11).
// ---------------------------------------------------------------------------
__global__ void __launch_bounds__(256) attn_kernel(const int* __restrict__ mask) {
    extern __shared__ char smem[];
    uint32_t* sKh = (uint32_t*)smem;                    // 16 KB, [blk][r][cp][half]
    uint32_t* sVp = sKh + KH * 4;                       // 16 KB
    uint32_t* sVm = sVp + KH * 4;                       //  2 KB

    int tid = threadIdx.x;
    int bh = blockIdx.x;
    int kh = blockIdx.z;                                // key half
    int b  = bh >> 4;
    int h  = bh & (NH - 1);

    {   // stage this half's keys with block-interleaved re-layout
        const uint4* gh = (const uint4*)(g_kh + ((size_t)bh * NS + kh * KH) * 4);
        const uint4* gv = (const uint4*)(g_vp + ((size_t)bh * (NS / 2) + kh * (KH / 2)) * 8);
        for (int s = tid; s < KH; s += 256) {
            uint4 k = gh[s];
            uint32_t* d = sKh + ((s >> 4) * 64 + (s & 7) * 8 + ((s >> 3) & 1));
            d[0] = k.x; d[2] = k.y; d[4] = k.z; d[6] = k.w;
        }
        for (int i = tid; i < KH; i += 256) {
            uint4 v = gv[i];
            int p = i >> 1;
            uint32_t* d = sVp + ((p >> 3) * 64 + (i & 1) * 32 + (p & 3) * 2 + ((p >> 2) & 1));
            d[0] = v.x; d[8] = v.y; d[16] = v.z; d[24] = v.w;
        }
        const int* mrow = mask + b * NS + kh * KH;
        for (int i = tid; i < KH / 2; i += 256) {
            __half m0 = __float2half_rn((float)mrow[2 * i]);
            __half m1 = __float2half_rn((float)mrow[2 * i + 1]);
            uint32_t pk = (uint32_t)__half_as_ushort(m0) | ((uint32_t)__half_as_ushort(m1) << 16);
            sVm[(i >> 3) * 8 + (i & 3) * 2 + ((i >> 2) & 1)] = pk;
        }
    }
    __syncthreads();

    int warp = tid >> 5, lane = tid & 31;
    int r0 = lane >> 2, cp = lane & 3;
    int qw = blockIdx.y * 128 + warp * 16;              // warp's first query

    const uint32_t* gkh = g_kh + (size_t)bh * NS * 4;
    uint32_t A0 = gkh[(qw + r0) * 4 + cp];
    uint32_t A1 = gkh[(qw + r0 + 8) * 4 + cp];

    float o[4]  = {0.f, 0.f, 0.f, 0.f};     // PV accumulator
    float o2[4] = {0.f, 0.f, 0.f, 0.f};     // den accumulator

    const int off  = r0 * 8 + cp * 2;
    const int offm = cp * 2;

#pragma unroll 4
    for (int it = 0; it < KH / 16; ++it) {
        uint2 kk = *(const uint2*)(sKh + it * 64 + off);   // {bh0, bh1}
        uint2 vv = *(const uint2*)(sVp + it * 64 + off);   // {vb0, vb1}
        uint2 mm = *(const uint2*)(sVm + it * 8 + offm);   // {vm0, vm1}

        uint32_t d0l, d0h, d1l, d1h;
        mma16808h(d0l, d0h, A0, A1, kk.x);                 // keys 0-7 of block
        mma16808h(d1l, d1h, A0, A1, kk.y);                 // keys 8-15

        uint32_t pe0 = ex2h2(d0l);   // row r0,   keys 2cp..2cp+1
        uint32_t pe1 = ex2h2(d0h);   // row r0+8
        uint32_t po0 = ex2h2(d1l);   // row r0,   keys 8+2cp
        uint32_t po1 = ex2h2(d1h);   // row r0+8

        mma16816(o,  pe0, pe1, po0, po1, vv.x, vv.y);      // numerator
        mma16816(o2, pe0, pe1, po0, po1, mm.x, mm.y);      // denominator
    }

    // write raw partials (den identical across cp columns; write once)
    float* nump = g_num[kh];
    size_t col = (size_t)h * ND + 2 * cp;
    float2* out0 = (float2*)(nump + ((size_t)(b * NS + qw + r0) * NE + col));
    float2* out1 = (float2*)(nump + ((size_t)(b * NS + qw + r0 + 8) * NE + col));
    *out0 = make_float2(o[0], o[1]);
    *out1 = make_float2(o[2], o[3]);
    if (cp == 0) {
        g_den[kh][(size_t)(b * NS + qw + r0) * NH + h]     = o2[0];
        g_den[kh][(size_t)(b * NS + qw + r0 + 8) * NH + h] = o2[2];
    }
}

// ---------------------------------------------------------------------------
// Kernel C (v2): fused combine + output GEMM.
// out[r, e] = sum_f ((n0[r,f]+n1[r,f]) * inv[r, f/8]) * w_out[e, f]
// 512 CTAs x 16 rows; 8 warps x 2 rows/warp; lane -> 4 output columns.
// Weights transposed+padded in SMEM; per-(row,head) inverses in SMEM.
// ---------------------------------------------------------------------------
__global__ void __launch_bounds__(256) out_kernel(const float* __restrict__ w,
                                                  float* __restrict__ out) {
    extern __shared__ float sW[];            // [128][132] + 256 invs
    float* sInv = sW + NE * 132;

    int tid = threadIdx.x;
    for (int i = tid; i < NE * NE; i += 256) {
        int e = i >> 7;
        int f = i & 127;
        sW[f * 132 + e] = w[i];
    }
    int rbase = blockIdx.x * 16;
    {   // per-(local row, head) inverse denominator: one per thread
        int r = rbase + (tid >> 4);
        int h = tid & 15;
        float den = g_den[0][(size_t)r * NH + h] + g_den[1][(size_t)r * NH + h];
        sInv[tid] = __fdividef(1.0f, fmaxf(den, 1e-30f));
    }
    __syncthreads();

    int warp = tid >> 5;
    int lane = tid & 31;

#pragma unroll
    for (int k = 0; k < 2; ++k) {
        int lr = warp * 2 + k;               // local row 0..15
        int r  = rbase + lr;
        const float4* n0 = (const float4*)(g_num[0] + (size_t)r * NE);
        const float4* n1 = (const float4*)(g_num[1] + (size_t)r * NE);
        const float* invs = sInv + lr * 16;

        float4 acc = make_float4(0.f, 0.f, 0.f, 0.f);
#pragma unroll
        for (int fi = 0; fi < 32; ++fi) {
            float4 a0 = n0[fi];
            float4 b0 = n1[fi];
            float inv = invs[fi >> 1];       // 8 floats per head = 2 float4s
            float ax = (a0.x + b0.x) * inv;
            float ay = (a0.y + b0.y) * inv;
            float az = (a0.z + b0.z) * inv;
            float aw = (a0.w + b0.w) * inv;
            int f = fi * 4;
            float4 w0 = *(const float4*)&sW[(f + 0) * 132 + lane * 4];
            acc.x = fmaf(ax, w0.x, acc.x);
            acc.y = fmaf(ax, w0.y, acc.y);
            acc.z = fmaf(ax, w0.z, acc.z);
            acc.w = fmaf(ax, w0.w, acc.w);
            float4 w1 = *(const float4*)&sW[(f + 1) * 132 + lane * 4];
            acc.x = fmaf(ay, w1.x, acc.x);
            acc.y = fmaf(ay, w1.y, acc.y);
            acc.z = fmaf(ay, w1.z, acc.z);
            acc.w = fmaf(ay, w1.w, acc.w);
            float4 w2 = *(const float4*)&sW[(f + 2) * 132 + lane * 4];
            acc.x = fmaf(az, w2.x, acc.x);
            acc.y = fmaf(az, w2.y, acc.y);
            acc.z = fmaf(az, w2.z, acc.z);
            acc.w = fmaf(az, w2.w, acc.w);
            float4 w3 = *(const float4*)&sW[(f + 3) * 132 + lane * 4];
            acc.x = fmaf(aw, w3.x, acc.x);
            acc.y = fmaf(aw, w3.y, acc.y);
            acc.z = fmaf(aw, w3.z, acc.z);
            acc.w = fmaf(aw, w3.w, acc.w);
        }
        *(float4*)(out + (size_t)r * NE + lane * 4) = acc;
    }
}

// ---------------------------------------------------------------------------
extern "C" void kernel_launch(void* const* d_in, const int* in_sizes, int n_in,
                              void* d_out, int out_size) {
    const float* x     = (const float*)d_in[0];
    const float* theta = (const float*)d_in[1];
    const float* w     = (const float*)d_in[2];
    const int*   mask  = (const int*)d_in[3];
    float*       out   = (float*)d_out;

    qgen_kernel<<<(NBH * NS) / 128, 128>>>(x, theta, mask);

    int smB = KH * 4 * 4 * 2 + (KH / 2) * 4;   // 32 KB K/V + 2 KB mask = 34816 B
    cudaFuncSetAttribute(attn_kernel, cudaFuncAttributeMaxDynamicSharedMemorySize, smB);
    attn_kernel<<<dim3(NBH, NS / 128, 2), 256, smB>>>(mask);

    int smC = NE * 132 * 4 + 256 * 4;          // 67584 + 1024 = 68608 B
    cudaFuncSetAttribute(out_kernel, cudaFuncAttributeMaxDynamicSharedMemorySize, smC);
    out_kernel<<<(NB * NS) / 16, 256, smC>>>(w, out);
}

// round 13
// speedup vs baseline: 4.9563x; 4.9563x over previous
#include <cuda_runtime.h>
#include <cuda_fp16.h>
#include <cstdint>

#define NB 4
#define NS 2048
#define NE 128
#define NH 16
#define ND 8
#define NBH (NB * NH)
#define KH 1024            // keys per CTA (half of NS)

// Staged head data (written by qgen, read by attn)
__device__ uint32_t g_kh[NBH * NS * 4];     // 2 MB fp16x2 CLS-scaled q/k
__device__ uint32_t g_vp[NBH * (NS/2) * 8]; // 2 MB pair-packed v*mask
__device__ float    g_num[2][NB * NS * NE]; // 8 MB partial numerators
__device__ float    g_den[2][NB * NS * NH]; // 1 MB partial denominators

__device__ __forceinline__ uint32_t ex2h2(uint32_t x) {
    uint32_t r; asm("ex2.approx.f16x2 %0,%1;" : "=r"(r) : "r"(x)); return r;
}
// score MMA: m16n8k8, fp16 accumulate -> D already packed f16x2
__device__ __forceinline__ void mma16808h(uint32_t& dlo, uint32_t& dhi,
                                          uint32_t a0, uint32_t a1, uint32_t b0) {
    asm volatile("mma.sync.aligned.m16n8k8.row.col.f16.f16.f16.f16 "
                 "{%0,%1},{%2,%3},{%4},{%5,%5};"
                 : "=r"(dlo), "=r"(dhi)
                 : "r"(a0), "r"(a1), "r"(b0), "r"(0u));
}
__device__ __forceinline__ void mma16816(float c[4],
                                         uint32_t a0, uint32_t a1, uint32_t a2, uint32_t a3,
                                         uint32_t b0, uint32_t b1) {
    asm volatile("mma.sync.aligned.m16n8k16.row.col.f32.f16.f16.f32 "
                 "{%0,%1,%2,%3},{%4,%5,%6,%7},{%8,%9},{%0,%1,%2,%3};"
                 : "+f"(c[0]), "+f"(c[1]), "+f"(c[2]), "+f"(c[3])
                 : "r"(a0), "r"(a1), "r"(a2), "r"(a3), "r"(b0), "r"(b1));
}

// ---------------------------------------------------------------------------
// Kernel A: q = cumprod(cos(x+theta)); emit sqrtCL-scaled fp16 pairs
// (score operands) + mask-folded pair-packed V.
// ---------------------------------------------------------------------------
__global__ void __launch_bounds__(128) qgen_kernel(const float* __restrict__ x,
                                                   const float* __restrict__ theta,
                                                   const int* __restrict__ mask) {
    int r = blockIdx.x * blockDim.x + threadIdx.x;   // r = bh*NS + s
    if (r >= NBH * NS) return;
    int s  = r & (NS - 1);
    int bh = r >> 11;
    int h  = bh & (NH - 1);
    int b  = bh >> 4;

    const float4* xp = (const float4*)(x + ((size_t)(b * NS + s) * NE + h * ND));
    float4 x0 = xp[0], x1 = xp[1];

    float v[8];
    float p;
    p  = cosf(x0.x + theta[0]);  v[0] = p;
    p *= cosf(x0.y + theta[1]);  v[1] = p;
    p *= cosf(x0.z + theta[2]);  v[2] = p;
    p *= cosf(x0.w + theta[3]);  v[3] = p;
    p *= cosf(x1.x + theta[4]);  v[4] = p;
    p *= cosf(x1.y + theta[5]);  v[5] = p;
    p *= cosf(x1.z + theta[6]);  v[6] = p;
    p *= cosf(x1.w + theta[7]);  v[7] = p;

    // sqrt(log2(e)/sqrt(8)) folded into BOTH score operands
    const float CLS = 0.71421430302f;   // sqrt(0.51010205144336435)
    uint32_t hw[4];
#pragma unroll
    for (int j = 0; j < 4; ++j) {
        __half h0 = __float2half_rn(v[2 * j] * CLS);
        __half h1 = __float2half_rn(v[2 * j + 1] * CLS);
        hw[j] = (uint32_t)__half_as_ushort(h0) | ((uint32_t)__half_as_ushort(h1) << 16);
    }
    ((uint4*)g_kh)[r] = make_uint4(hw[0], hw[1], hw[2], hw[3]);

    // pair-packed V with mask folded: g_vp[bh][s/2][n] = half2{v*m (even), (odd)}
    float m = (float)mask[b * NS + s];
    uint16_t* vp16 = (uint16_t*)g_vp;
    size_t base = (((size_t)bh * (NS / 2) + (s >> 1)) * 8) * 2 + (s & 1);
#pragma unroll
    for (int n = 0; n < 8; ++n)
        vp16[base + 2 * n] = __half_as_ushort(__float2half_rn(v[n] * m));
}

// ---------------------------------------------------------------------------
// Kernel B: HMMA flash attention, key-split for occupancy (unchanged from R11).
// ---------------------------------------------------------------------------
__global__ void __launch_bounds__(256) attn_kernel(const int* __restrict__ mask) {
    extern __shared__ char smem[];
    uint32_t* sKh = (uint32_t*)smem;                    // 16 KB, [blk][r][cp][half]
    uint32_t* sVp = sKh + KH * 4;                       // 16 KB
    uint32_t* sVm = sVp + KH * 4;                       //  2 KB

    int tid = threadIdx.x;
    int bh = blockIdx.x;
    int kh = blockIdx.z;                                // key half
    int b  = bh >> 4;
    int h  = bh & (NH - 1);

    {   // stage this half's keys with block-interleaved re-layout
        const uint4* gh = (const uint4*)(g_kh + ((size_t)bh * NS + kh * KH) * 4);
        const uint4* gv = (const uint4*)(g_vp + ((size_t)bh * (NS / 2) + kh * (KH / 2)) * 8);
        for (int s = tid; s < KH; s += 256) {
            uint4 k = gh[s];
            uint32_t* d = sKh + ((s >> 4) * 64 + (s & 7) * 8 + ((s >> 3) & 1));
            d[0] = k.x; d[2] = k.y; d[4] = k.z; d[6] = k.w;
        }
        for (int i = tid; i < KH; i += 256) {
            uint4 v = gv[i];
            int p = i >> 1;
            uint32_t* d = sVp + ((p >> 3) * 64 + (i & 1) * 32 + (p & 3) * 2 + ((p >> 2) & 1));
            d[0] = v.x; d[8] = v.y; d[16] = v.z; d[24] = v.w;
        }
        const int* mrow = mask + b * NS + kh * KH;
        for (int i = tid; i < KH / 2; i += 256) {
            __half m0 = __float2half_rn((float)mrow[2 * i]);
            __half m1 = __float2half_rn((float)mrow[2 * i + 1]);
            uint32_t pk = (uint32_t)__half_as_ushort(m0) | ((uint32_t)__half_as_ushort(m1) << 16);
            sVm[(i >> 3) * 8 + (i & 3) * 2 + ((i >> 2) & 1)] = pk;
        }
    }
    __syncthreads();

    int warp = tid >> 5, lane = tid & 31;
    int r0 = lane >> 2, cp = lane & 3;
    int qw = blockIdx.y * 128 + warp * 16;              // warp's first query

    const uint32_t* gkh = g_kh + (size_t)bh * NS * 4;
    uint32_t A0 = gkh[(qw + r0) * 4 + cp];
    uint32_t A1 = gkh[(qw + r0 + 8) * 4 + cp];

    float o[4]  = {0.f, 0.f, 0.f, 0.f};     // PV accumulator
    float o2[4] = {0.f, 0.f, 0.f, 0.f};     // den accumulator

    const int off  = r0 * 8 + cp * 2;
    const int offm = cp * 2;

#pragma unroll 4
    for (int it = 0; it < KH / 16; ++it) {
        uint2 kk = *(const uint2*)(sKh + it * 64 + off);   // {bh0, bh1}
        uint2 vv = *(const uint2*)(sVp + it * 64 + off);   // {vb0, vb1}
        uint2 mm = *(const uint2*)(sVm + it * 8 + offm);   // {vm0, vm1}

        uint32_t d0l, d0h, d1l, d1h;
        mma16808h(d0l, d0h, A0, A1, kk.x);                 // keys 0-7 of block
        mma16808h(d1l, d1h, A0, A1, kk.y);                 // keys 8-15

        uint32_t pe0 = ex2h2(d0l);   // row r0,   keys 2cp..2cp+1
        uint32_t pe1 = ex2h2(d0h);   // row r0+8
        uint32_t po0 = ex2h2(d1l);   // row r0,   keys 8+2cp
        uint32_t po1 = ex2h2(d1h);   // row r0+8

        mma16816(o,  pe0, pe1, po0, po1, vv.x, vv.y);      // numerator
        mma16816(o2, pe0, pe1, po0, po1, mm.x, mm.y);      // denominator
    }

    // write raw partials (den identical across cp columns; write once)
    float* nump = g_num[kh];
    size_t col = (size_t)h * ND + 2 * cp;
    float2* out0 = (float2*)(nump + ((size_t)(b * NS + qw + r0) * NE + col));
    float2* out1 = (float2*)(nump + ((size_t)(b * NS + qw + r0 + 8) * NE + col));
    *out0 = make_float2(o[0], o[1]);
    *out1 = make_float2(o[2], o[3]);
    if (cp == 0) {
        g_den[kh][(size_t)(b * NS + qw + r0) * NH + h]     = o2[0];
        g_den[kh][(size_t)(b * NS + qw + r0 + 8) * NH + h] = o2[2];
    }
}

// ---------------------------------------------------------------------------
// Kernel C (v3): fused combine + output GEMM, bounded unroll (NO spills).
// out[r, e] = sum_f ((n0[r,f]+n1[r,f]) * inv[r, f/8]) * w_out[e, f]
// 512 CTAs x 16 rows; 8 warps; each warp computes TWO rows interleaved in
// one fi loop (8 accumulators, weight LDS shared by both rows).
// ---------------------------------------------------------------------------
__global__ void __launch_bounds__(256) out_kernel(const float* __restrict__ w,
                                                  float* __restrict__ out) {
    extern __shared__ float sW[];            // [128][132] + 256 invs
    float* sInv = sW + NE * 132;

    int tid = threadIdx.x;
    for (int i = tid; i < NE * NE; i += 256) {
        int e = i >> 7;
        int f = i & 127;
        sW[f * 132 + e] = w[i];
    }
    int rbase = blockIdx.x * 16;
    {   // per-(local row, head) inverse denominator: one per thread
        int r = rbase + (tid >> 4);
        int h = tid & 15;
        float den = g_den[0][(size_t)r * NH + h] + g_den[1][(size_t)r * NH + h];
        sInv[tid] = __fdividef(1.0f, fmaxf(den, 1e-30f));
    }
    __syncthreads();

    int warp = tid >> 5;
    int lane = tid & 31;
    int rA = rbase + warp * 2;               // two rows per warp
    int rB = rA + 1;

    const float4* n0A = (const float4*)(g_num[0] + (size_t)rA * NE);
    const float4* n1A = (const float4*)(g_num[1] + (size_t)rA * NE);
    const float4* n0B = (const float4*)(g_num[0] + (size_t)rB * NE);
    const float4* n1B = (const float4*)(g_num[1] + (size_t)rB * NE);
    const float* invA = sInv + (warp * 2) * 16;
    const float* invB = invA + 16;

    float4 accA = make_float4(0.f, 0.f, 0.f, 0.f);
    float4 accB = make_float4(0.f, 0.f, 0.f, 0.f);

#pragma unroll 4
    for (int fi = 0; fi < 32; ++fi) {
        float4 a0 = n0A[fi], a1 = n1A[fi];
        float4 b0 = n0B[fi], b1 = n1B[fi];
        float iA = invA[fi >> 1];
        float iB = invB[fi >> 1];
        float axA = (a0.x + a1.x) * iA, ayA = (a0.y + a1.y) * iA;
        float azA = (a0.z + a1.z) * iA, awA = (a0.w + a1.w) * iA;
        float axB = (b0.x + b1.x) * iB, ayB = (b0.y + b1.y) * iB;
        float azB = (b0.z + b1.z) * iB, awB = (b0.w + b1.w) * iB;

        int f = fi * 4;
        float4 w0 = *(const float4*)&sW[(f + 0) * 132 + lane * 4];
        accA.x = fmaf(axA, w0.x, accA.x);  accB.x = fmaf(axB, w0.x, accB.x);
        accA.y = fmaf(axA, w0.y, accA.y);  accB.y = fmaf(axB, w0.y, accB.y);
        accA.z = fmaf(axA, w0.z, accA.z);  accB.z = fmaf(axB, w0.z, accB.z);
        accA.w = fmaf(axA, w0.w, accA.w);  accB.w = fmaf(axB, w0.w, accB.w);
        float4 w1 = *(const float4*)&sW[(f + 1) * 132 + lane * 4];
        accA.x = fmaf(ayA, w1.x, accA.x);  accB.x = fmaf(ayB, w1.x, accB.x);
        accA.y = fmaf(ayA, w1.y, accA.y);  accB.y = fmaf(ayB, w1.y, accB.y);
        accA.z = fmaf(ayA, w1.z, accA.z);  accB.z = fmaf(ayB, w1.z, accB.z);
        accA.w = fmaf(ayA, w1.w, accA.w);  accB.w = fmaf(ayB, w1.w, accB.w);
        float4 w2 = *(const float4*)&sW[(f + 2) * 132 + lane * 4];
        accA.x = fmaf(azA, w2.x, accA.x);  accB.x = fmaf(azB, w2.x, accB.x);
        accA.y = fmaf(azA, w2.y, accA.y);  accB.y = fmaf(azB, w2.y, accB.y);
        accA.z = fmaf(azA, w2.z, accA.z);  accB.z = fmaf(azB, w2.z, accB.z);
        accA.w = fmaf(azA, w2.w, accA.w);  accB.w = fmaf(azB, w2.w, accB.w);
        float4 w3 = *(const float4*)&sW[(f + 3) * 132 + lane * 4];
        accA.x = fmaf(awA, w3.x, accA.x);  accB.x = fmaf(awB, w3.x, accB.x);
        accA.y = fmaf(awA, w3.y, accA.y);  accB.y = fmaf(awB, w3.y, accB.y);
        accA.z = fmaf(awA, w3.z, accA.z);  accB.z = fmaf(awB, w3.z, accB.z);
        accA.w = fmaf(awA, w3.w, accA.w);  accB.w = fmaf(awB, w3.w, accB.w);
    }

    *(float4*)(out + (size_t)rA * NE + lane * 4) = accA;
    *(float4*)(out + (size_t)rB * NE + lane * 4) = accB;
}

// ---------------------------------------------------------------------------
extern "C" void kernel_launch(void* const* d_in, const int* in_sizes, int n_in,
                              void* d_out, int out_size) {
    const float* x     = (const float*)d_in[0];
    const float* theta = (const float*)d_in[1];
    const float* w     = (const float*)d_in[2];
    const int*   mask  = (const int*)d_in[3];
    float*       out   = (float*)d_out;

    qgen_kernel<<<(NBH * NS) / 128, 128>>>(x, theta, mask);

    int smB = KH * 4 * 4 * 2 + (KH / 2) * 4;   // 32 KB K/V + 2 KB mask = 34816 B
    cudaFuncSetAttribute(attn_kernel, cudaFuncAttributeMaxDynamicSharedMemorySize, smB);
    attn_kernel<<<dim3(NBH, NS / 128, 2), 256, smB>>>(mask);

    int smC = NE * 132 * 4 + 256 * 4;          // 67584 + 1024 = 68608 B
    cudaFuncSetAttribute(out_kernel, cudaFuncAttributeMaxDynamicSharedMemorySize, smC);
    out_kernel<<<(NB * NS) / 16, 256, smC>>>(w, out);
}